// round 15
// baseline (speedup 1.0000x reference)
#include <cuda_runtime.h>
#include <math.h>

#define N_NODES 8192
#define NTHREADS 256
#define CHUNKS 8
#define FLOAT4_PER_CHUNK ((long long)N_NODES / CHUNKS * N_NODES / 4)  // 2M

#define SCAT  160                 // scatter/rowsum blocks
#define ZEROB 1024                // zero blocks
#define NB (SCAT + ZEROB)         // 1184 = 148 SMs x 8 CTAs, all co-resident
#define F4_PER_BLOCK (FLOAT4_PER_CHUNK / ZEROB)          // 2048
#define F4_ITERS ((int)(F4_PER_BLOCK / NTHREADS))        // 8

// Device scratch (no cudaMalloc). All reset per replay via graph memset nodes.
__device__ float    g_rowsum[N_NODES];
__device__ unsigned g_done[CHUNKS];   // chunk-k zero completion counters
__device__ unsigned g_rsync;          // rowsum completion counter

__device__ __forceinline__ unsigned ld_volatile(const unsigned* p) {
    return *(volatile const unsigned*)p;
}

// ---------------------------------------------------------------------------
// Scatter edges with row in [rlo, rhi) (targets are L2-dirty, just zeroed).
// ---------------------------------------------------------------------------
__device__ __forceinline__ void scatter_range(const int* __restrict__ rows,
                                              const int* __restrict__ cols,
                                              const float* __restrict__ vals,
                                              float w, int E, int rlo, int rhi,
                                              float* __restrict__ out,
                                              int worker, int nworkers) {
    for (int i = worker; i < E; i += nworkers) {
        int r = __ldg(&rows[i]);
        if (r >= rlo && r < rhi) {
            float rs = g_rowsum[r];
            rs = (rs == 0.f) ? 1.f : rs;
            atomicAdd(&out[(long long)r * N_NODES + __ldg(&cols[i])],
                      __fdividef(w * __ldg(&vals[i]), rs));
        }
    }
}

// ---------------------------------------------------------------------------
// Single fused kernel: producer (zero) blocks free-run through all chunks;
// consumer (scatter) blocks follow one chunk behind via g_done counters.
// ---------------------------------------------------------------------------
__global__ void __launch_bounds__(NTHREADS, 8)
k_all(const int* __restrict__ rows_s, const int* __restrict__ cols_s,
      const float* __restrict__ vals_s,
      const int* __restrict__ rows_t, const int* __restrict__ cols_t,
      const float* __restrict__ vals_t,
      const float* __restrict__ gamma, float* __restrict__ out, int E) {
    int b = blockIdx.x;
    int t = threadIdx.x;

    if (b >= SCAT) {
        // ---------------- producer: stream zeros, never wait ----------------
        int zb = b - SCAT;                       // 0..ZEROB-1
        float4* out4 = (float4*)out;
        const float4 z = make_float4(0.f, 0.f, 0.f, 0.f);
#pragma unroll 1
        for (int k = 0; k < CHUNKS; k++) {
            long long base = (long long)k * FLOAT4_PER_CHUNK
                           + (long long)zb * F4_PER_BLOCK + t;
#pragma unroll
            for (int j = 0; j < F4_ITERS; j++)
                out4[base + (long long)j * NTHREADS] = z;
            __syncthreads();          // all threads' stores issued
            __threadfence();          // release: stores visible at L2
            if (t == 0) atomicAdd(&g_done[k], 1u);
        }
        return;
    }

    // ---------------- consumer: rowsum, then chase the producers ------------
    int worker = b * NTHREADS + t;
    int nw = SCAT * NTHREADS;
    float alpha = 1.0f / (1.0f + __expf(-gamma[0]));

    for (int i = worker; i < E; i += nw)
        atomicAdd(&g_rowsum[__ldg(&rows_s[i])], alpha * __ldg(&vals_s[i]));
    for (int i = worker; i < E; i += nw)
        atomicAdd(&g_rowsum[__ldg(&rows_t[i])],
                  (1.0f - alpha) * __ldg(&vals_t[i]));

    // all-scatter-block barrier on rowsum (producers are independent)
    __threadfence();
    __syncthreads();
    if (t == 0) {
        atomicAdd(&g_rsync, 1u);
        while (ld_volatile(&g_rsync) < SCAT) __nanosleep(32);
    }
    __syncthreads();

    const int rows_per_chunk = N_NODES / CHUNKS;
#pragma unroll 1
    for (int k = 0; k < CHUNKS; k++) {
        if (t == 0) {
            while (ld_volatile(&g_done[k]) < ZEROB) __nanosleep(64);
        }
        __syncthreads();
        __threadfence();  // acquire: order zero-stores before our atomics
        int rlo = k * rows_per_chunk, rhi = rlo + rows_per_chunk;
        scatter_range(rows_s, cols_s, vals_s, alpha, E, rlo, rhi, out,
                      worker, nw);
        scatter_range(rows_t, cols_t, vals_t, 1.0f - alpha, E, rlo, rhi, out,
                      worker, nw);
    }
}

// ---------------------------------------------------------------------------
// Launcher: memset scratch counters + rowsum, then ONE fused kernel.
// ---------------------------------------------------------------------------
extern "C" void kernel_launch(void* const* d_in, const int* in_sizes, int n_in,
                              void* d_out, int out_size) {
    const int*   rows_s = (const int*)d_in[0];
    const int*   cols_s = (const int*)d_in[1];
    const float* vals_s = (const float*)d_in[2];
    const int*   rows_t = (const int*)d_in[3];
    const int*   cols_t = (const int*)d_in[4];
    const float* vals_t = (const float*)d_in[5];
    const float* gamma  = (const float*)d_in[6];
    float* out = (float*)d_out;

    const int E = in_sizes[0];

    void *rowsum_ptr = nullptr, *done_ptr = nullptr, *rsync_ptr = nullptr;
    cudaGetSymbolAddress(&rowsum_ptr, g_rowsum);
    cudaGetSymbolAddress(&done_ptr, g_done);
    cudaGetSymbolAddress(&rsync_ptr, g_rsync);
    cudaMemsetAsync(rowsum_ptr, 0, N_NODES * sizeof(float));
    cudaMemsetAsync(done_ptr, 0, CHUNKS * sizeof(unsigned));
    cudaMemsetAsync(rsync_ptr, 0, sizeof(unsigned));

    k_all<<<NB, NTHREADS>>>(rows_s, cols_s, vals_s,
                            rows_t, cols_t, vals_t,
                            gamma, out, E);
}

// round 17
// speedup vs baseline: 1.5505x; 1.5505x over previous
#include <cuda_runtime.h>
#include <math.h>

#define N_NODES 8192
#define NTHREADS 256
#define CHUNKS 8
#define ROWS_PER_CHUNK (N_NODES / CHUNKS)                           // 1024
#define FLOAT4_PER_CHUNK ((long long)ROWS_PER_CHUNK * N_NODES / 4)  // 2M
#define ZERO_BLOCKS 1024
#define F4_ITERS ((int)(FLOAT4_PER_CHUNK / (ZERO_BLOCKS * NTHREADS)))  // 8

// Row-sum scratch (no cudaMalloc allowed); zeroed via graph memset node.
__device__ float g_rowsum[N_NODES];

// ---------------------------------------------------------------------------
// Rowsum: weighted per-row sums from both edge lists (RED.ADD, L2-resident).
// ---------------------------------------------------------------------------
__global__ void __launch_bounds__(NTHREADS)
k_rowsum(const int* __restrict__ rows_s, const float* __restrict__ vals_s,
         const int* __restrict__ rows_t, const float* __restrict__ vals_t,
         const float* __restrict__ gamma, int E) {
    int i = blockIdx.x * NTHREADS + threadIdx.x;
    float alpha = 1.0f / (1.0f + __expf(-gamma[0]));
    if (i < E) {
        atomicAdd(&g_rowsum[rows_s[i]], alpha * vals_s[i]);
    } else if (i < 2 * E) {
        int j = i - E;
        atomicAdd(&g_rowsum[rows_t[j]], (1.0f - alpha) * vals_t[j]);
    }
}

// ---------------------------------------------------------------------------
// Zero one 32MB chunk. Default-cached stores: the lines stay dirty in L2 so
// the overlapped scatter kernel's atomics hit L2 instead of DRAM.
// ---------------------------------------------------------------------------
__global__ void __launch_bounds__(NTHREADS)
k_zero(float4* __restrict__ out4, int k) {
    long long base = (long long)k * FLOAT4_PER_CHUNK
                   + (long long)blockIdx.x * (F4_ITERS * NTHREADS)
                   + threadIdx.x;
    const float4 z = make_float4(0.f, 0.f, 0.f, 0.f);
#pragma unroll
    for (int j = 0; j < F4_ITERS; j++)
        out4[base + (long long)j * NTHREADS] = z;
}

// ---------------------------------------------------------------------------
// Scatter edges whose row is in chunk k (targets just zeroed -> L2 hits).
// ---------------------------------------------------------------------------
__global__ void __launch_bounds__(NTHREADS)
k_scatter(const int* __restrict__ rows_s, const int* __restrict__ cols_s,
          const float* __restrict__ vals_s,
          const int* __restrict__ rows_t, const int* __restrict__ cols_t,
          const float* __restrict__ vals_t,
          const float* __restrict__ gamma, float* __restrict__ out,
          int E, int rlo, int rhi) {
    int i = blockIdx.x * NTHREADS + threadIdx.x;
    float alpha = 1.0f / (1.0f + __expf(-gamma[0]));
    int r, c; float v;
    if (i < E) {
        r = rows_s[i];
        if (r < rlo || r >= rhi) return;
        c = cols_s[i];
        v = alpha * vals_s[i];
    } else if (i < 2 * E) {
        int j = i - E;
        r = rows_t[j];
        if (r < rlo || r >= rhi) return;
        c = cols_t[j];
        v = (1.0f - alpha) * vals_t[j];
    } else {
        return;
    }
    float rs = g_rowsum[r];
    rs = (rs == 0.f) ? 1.f : rs;
    atomicAdd(&out[(long long)r * N_NODES + c], __fdividef(v, rs));
}

// ---------------------------------------------------------------------------
// Launcher: two streams, event-gated per-chunk dependencies. Hardware
// scheduler overlaps the zero stream with rowsum + per-chunk scatters.
// Streams/events are host resources (not device memory) created once.
// ---------------------------------------------------------------------------
extern "C" void kernel_launch(void* const* d_in, const int* in_sizes, int n_in,
                              void* d_out, int out_size) {
    const int*   rows_s = (const int*)d_in[0];
    const int*   cols_s = (const int*)d_in[1];
    const float* vals_s = (const float*)d_in[2];
    const int*   rows_t = (const int*)d_in[3];
    const int*   cols_t = (const int*)d_in[4];
    const float* vals_t = (const float*)d_in[5];
    const float* gamma  = (const float*)d_in[6];
    float* out = (float*)d_out;

    const int E = in_sizes[0];
    const int total = 2 * E;

    static cudaStream_t s_zero = nullptr;
    static cudaEvent_t  e_fork = nullptr;
    static cudaEvent_t  e_z[CHUNKS];
    if (!s_zero) {
        cudaStreamCreateWithFlags(&s_zero, cudaStreamNonBlocking);
        cudaEventCreateWithFlags(&e_fork, cudaEventDisableTiming);
        for (int k = 0; k < CHUNKS; k++)
            cudaEventCreateWithFlags(&e_z[k], cudaEventDisableTiming);
    }

    // kernel_launch is invoked on the harness's (capture) stream = default
    // stream for these launches: use the legacy default stream handle 0.
    cudaStream_t s_main = 0;

    // Fork: s_zero joins the capture DAG by waiting on an event from s_main.
    cudaEventRecord(e_fork, s_main);
    cudaStreamWaitEvent(s_zero, e_fork, 0);

    // Zero stream: 8 x 32MB chunk zero kernels, each followed by its event.
    for (int k = 0; k < CHUNKS; k++) {
        k_zero<<<ZERO_BLOCKS, NTHREADS, 0, s_zero>>>((float4*)out, k);
        cudaEventRecord(e_z[k], s_zero);
    }

    // Main stream: rowsum scratch memset + rowsum (overlaps early zeros).
    void* rowsum_ptr = nullptr;
    cudaGetSymbolAddress(&rowsum_ptr, g_rowsum);
    cudaMemsetAsync(rowsum_ptr, 0, N_NODES * sizeof(float), s_main);
    k_rowsum<<<(total + NTHREADS - 1) / NTHREADS, NTHREADS, 0, s_main>>>(
        rows_s, vals_s, rows_t, vals_t, gamma, E);

    // Per-chunk scatter, each gated on its chunk's zero completion.
    // (Joins every s_zero node into the main-stream chain as well.)
    for (int k = 0; k < CHUNKS; k++) {
        cudaStreamWaitEvent(s_main, e_z[k], 0);
        k_scatter<<<(total + NTHREADS - 1) / NTHREADS, NTHREADS, 0, s_main>>>(
            rows_s, cols_s, vals_s, rows_t, cols_t, vals_t, gamma, out, E,
            k * ROWS_PER_CHUNK, (k + 1) * ROWS_PER_CHUNK);
    }
}